// round 7
// baseline (speedup 1.0000x reference)
#include <cuda_runtime.h>
#include <cuda_bf16.h>
#include <cuda_fp16.h>
#include <cstdint>
#include <math.h>

#define N_NODES 100000
#define N_EDGES 1600000
#define IN_C 128
#define HID_C 128
#define OUT_C 64
#define SCAN_BLOCKS 256
#define NTILES 782           // ceil(100000/128)

// ---------------- scratch (static device globals; no allocation) ----------------
__device__ int   g_deg[N_NODES];
__device__ float g_dinv[N_NODES];
__device__ int   g_rowptr[N_NODES + 1];
__device__ int   g_cursor[N_NODES];
__device__ int2  g_cw[N_EDGES];          // packed (src, wgt-bits)
__device__ int   g_blocksums[SCAN_BLOCKS];
__device__ __align__(16) __half g_h1h[(size_t)N_NODES * HID_C];
__device__ __align__(16) __half g_h2h[(size_t)N_NODES * OUT_C];
__device__ __align__(16) __nv_bfloat16 g_w1hi[128 * 128];
__device__ __align__(16) __nv_bfloat16 g_w1lo[128 * 128];
__device__ __align__(16) __nv_bfloat16 g_w2hi[64 * 128];
__device__ __align__(16) __nv_bfloat16 g_w2lo[64 * 128];

// ---------------- degree / scan / CSR ----------------
__global__ void k_count(const int4* __restrict__ dst4) {
    int i = blockIdx.x * 256 + threadIdx.x;
    if (i < N_EDGES / 4) {
        int4 d = __ldg(&dst4[i]);
        atomicAdd(&g_deg[d.x], 1);
        atomicAdd(&g_deg[d.y], 1);
        atomicAdd(&g_deg[d.z], 1);
        atomicAdd(&g_deg[d.w], 1);
    }
}

__global__ void k_scan_part() {
    __shared__ int wsum[16];
    int tid = threadIdx.x;
    int lane = tid & 31, wid = tid >> 5;
    int i = blockIdx.x * 512 + tid;
    int c = 0;
    if (i < N_NODES) {
        int d = g_deg[i];
        g_dinv[i] = rsqrtf((float)(d + 1));
        c = d;
    }
    int v = c;
    #pragma unroll
    for (int o = 1; o < 32; o <<= 1) {
        int t = __shfl_up_sync(0xffffffffu, v, o);
        if (lane >= o) v += t;
    }
    if (lane == 31) wsum[wid] = v;
    __syncthreads();
    if (wid == 0) {
        int s = (lane < 16) ? wsum[lane] : 0;
        #pragma unroll
        for (int o = 1; o < 16; o <<= 1) {
            int t = __shfl_up_sync(0xffffffffu, s, o);
            if (lane >= o) s += t;
        }
        if (lane < 16) wsum[lane] = s;
    }
    __syncthreads();
    int off = (wid > 0) ? wsum[wid - 1] : 0;
    if (i < N_NODES) g_rowptr[i] = off + v - c;
    if (tid == 511) g_blocksums[blockIdx.x] = wsum[15];
}

__global__ void k_scan_add2() {
    __shared__ int bs[SCAN_BLOCKS];
    __shared__ int pre[SCAN_BLOCKS];
    int tid = threadIdx.x;
    if (tid < SCAN_BLOCKS) bs[tid] = g_blocksums[tid];
    __syncthreads();
    if (tid < SCAN_BLOCKS) {
        int acc = 0;
        for (int j = 0; j < SCAN_BLOCKS; j++) {
            int v = bs[j];
            if (j < tid) acc += v;
        }
        pre[tid] = acc;
    }
    __syncthreads();
    int i = blockIdx.x * 512 + tid;
    if (i < N_NODES) {
        int r = g_rowptr[i] + pre[i >> 9];
        g_rowptr[i] = r;
        g_cursor[i] = r;
    }
    if (i == N_NODES) g_rowptr[N_NODES] = N_EDGES;
}

__global__ void k_fill(const int4* __restrict__ src4, const int4* __restrict__ dst4) {
    int i = blockIdx.x * 256 + threadIdx.x;
    if (i < N_EDGES / 4) {
        int4 s = __ldg(&src4[i]);
        int4 d = __ldg(&dst4[i]);
        int p0 = atomicAdd(&g_cursor[d.x], 1);
        g_cw[p0] = make_int2(s.x, __float_as_int(g_dinv[s.x]));
        int p1 = atomicAdd(&g_cursor[d.y], 1);
        g_cw[p1] = make_int2(s.y, __float_as_int(g_dinv[s.y]));
        int p2 = atomicAdd(&g_cursor[d.z], 1);
        g_cw[p2] = make_int2(s.z, __float_as_int(g_dinv[s.z]));
        int p3 = atomicAdd(&g_cursor[d.w], 1);
        g_cw[p3] = make_int2(s.w, __float_as_int(g_dinv[s.w]));
    }
}

// ---------------- prep: split W into bf16 hi/lo, [n][k] orientation ----------------
__global__ void k_prep_w(const float* __restrict__ W1, const float* __restrict__ W2) {
    int i = blockIdx.x * 256 + threadIdx.x;
    if (i < 128 * 128) {
        int k = i >> 7, n = i & 127;
        float v = W1[i];
        __nv_bfloat16 h = __float2bfloat16(v);
        __nv_bfloat16 l = __float2bfloat16(v - __bfloat162float(h));
        g_w1hi[n * 128 + k] = h;
        g_w1lo[n * 128 + k] = l;
    } else if (i < 128 * 128 + 64 * 128) {
        int j = i - 128 * 128;
        int k = j >> 6, n = j & 63;
        float v = W2[j];
        __nv_bfloat16 h = __float2bfloat16(v);
        __nv_bfloat16 l = __float2bfloat16(v - __bfloat162float(h));
        g_w2hi[n * 128 + k] = h;
        g_w2lo[n * 128 + k] = l;
    }
}

// ---------------- bf16 mma.sync helper ----------------
__device__ __forceinline__ void mma_bf16(float& d0, float& d1, float& d2, float& d3,
                                         uint32_t a0, uint32_t a1, uint32_t a2, uint32_t a3,
                                         uint32_t b0, uint32_t b1) {
    asm volatile(
        "mma.sync.aligned.m16n8k16.row.col.f32.bf16.bf16.f32 "
        "{%0,%1,%2,%3}, {%4,%5,%6,%7}, {%8,%9}, {%0,%1,%2,%3};"
        : "+f"(d0), "+f"(d1), "+f"(d2), "+f"(d3)
        : "r"(a0), "r"(a1), "r"(a2), "r"(a3), "r"(b0), "r"(b1));
}
__device__ __forceinline__ uint32_t pack_hi2(float x, float y) {
    __nv_bfloat162 t = __halves2bfloat162(__float2bfloat16(x), __float2bfloat16(y));
    return *(uint32_t*)&t;
}
__device__ __forceinline__ uint32_t pack_lo2(float x, float y) {
    __nv_bfloat16 hx = __float2bfloat16(x), hy = __float2bfloat16(y);
    __nv_bfloat162 t = __halves2bfloat162(__float2bfloat16(x - __bfloat162float(hx)),
                                          __float2bfloat16(y - __bfloat162float(hy)));
    return *(uint32_t*)&t;
}
__device__ __forceinline__ void fma_h4(float4& acc, float w, uint2 rv) {
    float2 f0 = __half22float2(*(__half2*)&rv.x);
    float2 f1 = __half22float2(*(__half2*)&rv.y);
    acc.x = fmaf(w, f0.x, acc.x);
    acc.y = fmaf(w, f0.y, acc.y);
    acc.z = fmaf(w, f1.x, acc.z);
    acc.w = fmaf(w, f1.y, acc.w);
}

// ---------------- GEMM1: h1h = x @ W1 (tensor cores, hi/lo split) ----------------
__global__ __launch_bounds__(256) void k_gemm1(const float* __restrict__ Ain) {
    extern __shared__ uint32_t smu[];
    constexpr int STR = 68;
    uint32_t* As_hi = smu;
    uint32_t* As_lo = As_hi + 128 * STR;
    uint32_t* Bs_hi = As_lo + 128 * STR;
    uint32_t* Bs_lo = Bs_hi + 128 * STR;

    const int tid = threadIdx.x;
    const int wid = tid >> 5;
    const int lane = tid & 31;
    const int g = lane >> 2;
    const int tg = lane & 3;
    const int row0 = blockIdx.x * 128;

    const float4* A4 = (const float4*)Ain;
    #pragma unroll 4
    for (int t = 0; t < 16; t++) {
        int i = t * 256 + tid;
        int row = i >> 5, c4 = i & 31;
        int gr = row0 + row;
        float4 v = make_float4(0.f, 0.f, 0.f, 0.f);
        if (gr < N_NODES) v = A4[(size_t)gr * 32 + c4];
        *(uint2*)&As_hi[row * STR + c4 * 2] = make_uint2(pack_hi2(v.x, v.y), pack_hi2(v.z, v.w));
        *(uint2*)&As_lo[row * STR + c4 * 2] = make_uint2(pack_lo2(v.x, v.y), pack_lo2(v.z, v.w));
    }
    const uint32_t* WhG = (const uint32_t*)g_w1hi;
    const uint32_t* WlG = (const uint32_t*)g_w1lo;
    for (int i = tid; i < 128 * 64; i += 256) {
        int n = i >> 6, kp = i & 63;
        Bs_hi[n * STR + kp] = WhG[i];
        Bs_lo[n * STR + kp] = WlG[i];
    }
    __syncthreads();

    const int wm = wid & 1;        // 2 M-groups of 64
    const int wn = wid >> 1;       // 4 N-groups of 32
    float d[4][4][4];
    #pragma unroll
    for (int mt = 0; mt < 4; mt++)
        #pragma unroll
        for (int nt = 0; nt < 4; nt++)
            #pragma unroll
            for (int j = 0; j < 4; j++) d[mt][nt][j] = 0.f;

    const uint32_t* Aterm[3] = {As_hi, As_hi, As_lo};
    const uint32_t* Bterm[3] = {Bs_hi, Bs_lo, Bs_hi};

    #pragma unroll
    for (int term = 0; term < 3; term++) {
        const uint32_t* Ab = Aterm[term] + (wm * 64 + g) * STR;
        const uint32_t* Bb = Bterm[term] + (wn * 32 + g) * STR;
        #pragma unroll
        for (int ks = 0; ks < 8; ks++) {
            int ko = ks * 8 + tg;
            uint32_t a[4][4], b[4][2];
            #pragma unroll
            for (int mt = 0; mt < 4; mt++) {
                const uint32_t* Ar = Ab + mt * 16 * STR;
                a[mt][0] = Ar[ko];
                a[mt][1] = Ar[8 * STR + ko];
                a[mt][2] = Ar[ko + 4];
                a[mt][3] = Ar[8 * STR + ko + 4];
            }
            #pragma unroll
            for (int nt = 0; nt < 4; nt++) {
                const uint32_t* Br = Bb + nt * 8 * STR;
                b[nt][0] = Br[ko];
                b[nt][1] = Br[ko + 4];
            }
            #pragma unroll
            for (int mt = 0; mt < 4; mt++)
                #pragma unroll
                for (int nt = 0; nt < 4; nt++)
                    mma_bf16(d[mt][nt][0], d[mt][nt][1], d[mt][nt][2], d[mt][nt][3],
                             a[mt][0], a[mt][1], a[mt][2], a[mt][3],
                             b[nt][0], b[nt][1]);
        }
    }

    #pragma unroll
    for (int mt = 0; mt < 4; mt++) {
        int r0 = row0 + wm * 64 + mt * 16 + g;
        #pragma unroll
        for (int nt = 0; nt < 4; nt++) {
            int c = wn * 32 + nt * 8 + tg * 2;
            if (r0 < N_NODES)
                *(__half2*)&g_h1h[(size_t)r0 * 128 + c] =
                    __floats2half2_rn(d[mt][nt][0], d[mt][nt][1]);
            if (r0 + 8 < N_NODES)
                *(__half2*)&g_h1h[(size_t)(r0 + 8) * 128 + c] =
                    __floats2half2_rn(d[mt][nt][2], d[mt][nt][3]);
        }
    }
}

// ---------------- FUSED: agg1(+bias+relu) into smem, then GEMM2 -> h2h ----------------
__global__ __launch_bounds__(256) void k_agg1_gemm2(const float* __restrict__ b1) {
    extern __shared__ uint32_t smu[];
    constexpr int STR = 68;
    uint32_t* As_hi = smu;                    // 128 x STR
    uint32_t* As_lo = As_hi + 128 * STR;
    uint32_t* Bs_hi = As_lo + 128 * STR;      // 64 x STR
    uint32_t* Bs_lo = Bs_hi + 64 * STR;

    const int tid = threadIdx.x;
    const int wid = tid >> 5;
    const int lane = tid & 31;
    const int g = lane >> 2;
    const int tg = lane & 3;
    const int row0 = blockIdx.x * 128;

    // stage B weights
    const uint32_t* WhG = (const uint32_t*)g_w2hi;
    const uint32_t* WlG = (const uint32_t*)g_w2lo;
    for (int i = tid; i < 64 * 64; i += 256) {
        int n = i >> 6, kp = i & 63;
        Bs_hi[n * STR + kp] = WhG[i];
        Bs_lo[n * STR + kp] = WlG[i];
    }

    // stage A: aggregate 16 nodes per warp, write bf16 hi/lo to smem
    const uint2* H = (const uint2*)g_h1h;
    float4 bv = ((const float4*)b1)[lane];
    for (int i = 0; i < 16; i++) {
        int r = wid * 16 + i;
        int node = row0 + r;
        float4 acc = make_float4(0.f, 0.f, 0.f, 0.f);
        if (node < N_NODES) {
            float di = g_dinv[node];
            uint2 sv = __ldg(&H[(size_t)node * 32 + lane]);
            fma_h4(acc, di, sv);
            int beg = g_rowptr[node];
            int end = g_rowptr[node + 1];
            #pragma unroll 8
            for (int e = beg; e < end; e++) {
                int2 cw = __ldg(&g_cw[e]);
                float w = __int_as_float(cw.y);
                uint2 hv = __ldg(&H[(size_t)cw.x * 32 + lane]);
                fma_h4(acc, w, hv);
            }
            acc.x = fmaxf(fmaf(acc.x, di, bv.x), 0.f);
            acc.y = fmaxf(fmaf(acc.y, di, bv.y), 0.f);
            acc.z = fmaxf(fmaf(acc.z, di, bv.z), 0.f);
            acc.w = fmaxf(fmaf(acc.w, di, bv.w), 0.f);
        }
        *(uint2*)&As_hi[r * STR + lane * 2] = make_uint2(pack_hi2(acc.x, acc.y), pack_hi2(acc.z, acc.w));
        *(uint2*)&As_lo[r * STR + lane * 2] = make_uint2(pack_lo2(acc.x, acc.y), pack_lo2(acc.z, acc.w));
    }
    __syncthreads();

    // MMA phase: 128x64x128, warp tile 32x32 (wm = wid&3, wn = wid>>2)
    const int wm = wid & 3;
    const int wn = wid >> 2;
    float d[2][4][4];
    #pragma unroll
    for (int mt = 0; mt < 2; mt++)
        #pragma unroll
        for (int nt = 0; nt < 4; nt++)
            #pragma unroll
            for (int j = 0; j < 4; j++) d[mt][nt][j] = 0.f;

    const uint32_t* Aterm[3] = {As_hi, As_hi, As_lo};
    const uint32_t* Bterm[3] = {Bs_hi, Bs_lo, Bs_hi};

    #pragma unroll
    for (int term = 0; term < 3; term++) {
        const uint32_t* Ab = Aterm[term] + (wm * 32 + g) * STR;
        const uint32_t* Bb = Bterm[term] + (wn * 32 + g) * STR;
        #pragma unroll
        for (int ks = 0; ks < 8; ks++) {
            int ko = ks * 8 + tg;
            uint32_t a[2][4], b[4][2];
            #pragma unroll
            for (int mt = 0; mt < 2; mt++) {
                const uint32_t* Ar = Ab + mt * 16 * STR;
                a[mt][0] = Ar[ko];
                a[mt][1] = Ar[8 * STR + ko];
                a[mt][2] = Ar[ko + 4];
                a[mt][3] = Ar[8 * STR + ko + 4];
            }
            #pragma unroll
            for (int nt = 0; nt < 4; nt++) {
                const uint32_t* Br = Bb + nt * 8 * STR;
                b[nt][0] = Br[ko];
                b[nt][1] = Br[ko + 4];
            }
            #pragma unroll
            for (int mt = 0; mt < 2; mt++)
                #pragma unroll
                for (int nt = 0; nt < 4; nt++)
                    mma_bf16(d[mt][nt][0], d[mt][nt][1], d[mt][nt][2], d[mt][nt][3],
                             a[mt][0], a[mt][1], a[mt][2], a[mt][3],
                             b[nt][0], b[nt][1]);
        }
    }

    #pragma unroll
    for (int mt = 0; mt < 2; mt++) {
        int r0 = row0 + wm * 32 + mt * 16 + g;
        #pragma unroll
        for (int nt = 0; nt < 4; nt++) {
            int c = wn * 32 + nt * 8 + tg * 2;
            if (r0 < N_NODES)
                *(__half2*)&g_h2h[(size_t)r0 * 64 + c] =
                    __floats2half2_rn(d[mt][nt][0], d[mt][nt][1]);
            if (r0 + 8 < N_NODES)
                *(__half2*)&g_h2h[(size_t)(r0 + 8) * 64 + c] =
                    __floats2half2_rn(d[mt][nt][2], d[mt][nt][3]);
        }
    }
}

// ---------------- aggregate layer 2 (fp16 gathers) + bias + log_softmax ----------------
__global__ __launch_bounds__(256) void k_agg2(const float* __restrict__ b2,
                                              float* __restrict__ out) {
    int node = blockIdx.x * 8 + (threadIdx.x >> 5);
    if (node >= N_NODES) return;
    int lane = threadIdx.x & 31;
    float di = g_dinv[node];
    const __half2* H = (const __half2*)g_h2h;
    float2 self = __half22float2(__ldg(&H[(size_t)node * 32 + lane]));
    float2 acc = make_float2(di * self.x, di * self.y);
    int beg = g_rowptr[node];
    int end = g_rowptr[node + 1];
    #pragma unroll 8
    for (int e = beg; e < end; e++) {
        int2 cw = __ldg(&g_cw[e]);
        float w = __int_as_float(cw.y);
        float2 hv = __half22float2(__ldg(&H[(size_t)cw.x * 32 + lane]));
        acc.x = fmaf(w, hv.x, acc.x);
        acc.y = fmaf(w, hv.y, acc.y);
    }
    float2 bv = ((const float2*)b2)[lane];
    float vx = fmaf(acc.x, di, bv.x);
    float vy = fmaf(acc.y, di, bv.y);

    float m = fmaxf(vx, vy);
    #pragma unroll
    for (int o = 16; o > 0; o >>= 1) m = fmaxf(m, __shfl_xor_sync(0xffffffffu, m, o));
    float s = expf(vx - m) + expf(vy - m);
    #pragma unroll
    for (int o = 16; o > 0; o >>= 1) s += __shfl_xor_sync(0xffffffffu, s, o);
    float lse = m + logf(s);
    ((float2*)out)[(size_t)node * 32 + lane] = make_float2(vx - lse, vy - lse);
}

// ---------------- launch ----------------
extern "C" void kernel_launch(void* const* d_in, const int* in_sizes, int n_in,
                              void* d_out, int out_size) {
    const float* x  = (const float*)d_in[0];
    const int*   ei = (const int*)d_in[1];
    const float* W1 = (const float*)d_in[2];
    const float* b1 = (const float*)d_in[3];
    const float* W2 = (const float*)d_in[4];
    const float* b2 = (const float*)d_in[5];
    float* out = (float*)d_out;

    const int4* src4 = (const int4*)ei;
    const int4* dst4 = (const int4*)(ei + N_EDGES);

    const int SMEM1 = (2 * 128 * 68 + 2 * 128 * 68) * 4;  // 139264
    const int SMEMF = (2 * 128 * 68 + 2 * 64 * 68) * 4;   // 104448
    cudaFuncSetAttribute(k_gemm1, cudaFuncAttributeMaxDynamicSharedMemorySize, SMEM1);
    cudaFuncSetAttribute(k_agg1_gemm2, cudaFuncAttributeMaxDynamicSharedMemorySize, SMEMF);

    void* degptr = nullptr;
    cudaGetSymbolAddress(&degptr, g_deg);

    cudaStream_t s1;
    cudaStreamCreateWithFlags(&s1, cudaStreamNonBlocking);
    cudaEvent_t evFork, evG1;
    cudaEventCreateWithFlags(&evFork, cudaEventDisableTiming);
    cudaEventCreateWithFlags(&evG1, cudaEventDisableTiming);

    cudaEventRecord(evFork, 0);
    cudaStreamWaitEvent(s1, evFork, 0);

    // side stream: weight prep + GEMM1 (independent of graph structure)
    k_prep_w<<<(128 * 128 + 64 * 128 + 255) / 256, 256, 0, s1>>>(W1, W2);
    k_gemm1<<<NTILES, 256, SMEM1, s1>>>(x);
    cudaEventRecord(evG1, s1);

    // main stream: CSR build
    cudaMemsetAsync(degptr, 0, N_NODES * sizeof(int));
    k_count<<<(N_EDGES / 4 + 255) / 256, 256>>>(dst4);
    k_scan_part<<<SCAN_BLOCKS, 512>>>();
    k_scan_add2<<<(N_NODES + 512) / 512, 512>>>();
    k_fill<<<(N_EDGES / 4 + 255) / 256, 256>>>(src4, dst4);

    cudaStreamWaitEvent(0, evG1, 0);

    k_agg1_gemm2<<<NTILES, 256, SMEMF>>>(b1);
    k_agg2<<<(N_NODES + 7) / 8, 256>>>(b2, out);
}

// round 8
// speedup vs baseline: 1.5507x; 1.5507x over previous
#include <cuda_runtime.h>
#include <cuda_bf16.h>
#include <cuda_fp16.h>
#include <cstdint>
#include <math.h>

#define N_NODES 100000
#define N_EDGES 1600000
#define IN_C 128
#define HID_C 128
#define OUT_C 64
#define SCAN_BLOCKS 256
#define NTILES 782           // ceil(100000/128)
#define CHUNKS 6
#define TILES_PER_CHUNK 131  // 131*128 nodes per chunk; last chunk = 782-5*131 = 127 tiles

// ---------------- scratch (static device globals; no allocation) ----------------
__device__ int   g_deg[N_NODES];
__device__ float g_dinv[N_NODES];
__device__ int   g_rowptr[N_NODES + 1];
__device__ int   g_cursor[N_NODES];
__device__ int2  g_cw[N_EDGES];          // packed (src, wgt-bits)
__device__ int   g_blocksums[SCAN_BLOCKS];
__device__ __align__(16) __half g_h1h[(size_t)N_NODES * HID_C];
__device__ __align__(16) float  g_a1[(size_t)N_NODES * HID_C];
__device__ __align__(16) __half g_h2h[(size_t)N_NODES * OUT_C];
__device__ __align__(16) __nv_bfloat16 g_w1hi[128 * 128];
__device__ __align__(16) __nv_bfloat16 g_w1lo[128 * 128];
__device__ __align__(16) __nv_bfloat16 g_w2hi[64 * 128];
__device__ __align__(16) __nv_bfloat16 g_w2lo[64 * 128];

// ---------------- degree / scan / CSR ----------------
__global__ void k_count(const int4* __restrict__ dst4) {
    int i = blockIdx.x * 256 + threadIdx.x;
    if (i < N_EDGES / 4) {
        int4 d = __ldg(&dst4[i]);
        atomicAdd(&g_deg[d.x], 1);
        atomicAdd(&g_deg[d.y], 1);
        atomicAdd(&g_deg[d.z], 1);
        atomicAdd(&g_deg[d.w], 1);
    }
}

__global__ void k_scan_part() {
    __shared__ int wsum[16];
    int tid = threadIdx.x;
    int lane = tid & 31, wid = tid >> 5;
    int i = blockIdx.x * 512 + tid;
    int c = 0;
    if (i < N_NODES) {
        int d = g_deg[i];
        g_dinv[i] = rsqrtf((float)(d + 1));
        c = d;
    }
    int v = c;
    #pragma unroll
    for (int o = 1; o < 32; o <<= 1) {
        int t = __shfl_up_sync(0xffffffffu, v, o);
        if (lane >= o) v += t;
    }
    if (lane == 31) wsum[wid] = v;
    __syncthreads();
    if (wid == 0) {
        int s = (lane < 16) ? wsum[lane] : 0;
        #pragma unroll
        for (int o = 1; o < 16; o <<= 1) {
            int t = __shfl_up_sync(0xffffffffu, s, o);
            if (lane >= o) s += t;
        }
        if (lane < 16) wsum[lane] = s;
    }
    __syncthreads();
    int off = (wid > 0) ? wsum[wid - 1] : 0;
    if (i < N_NODES) g_rowptr[i] = off + v - c;
    if (tid == 511) g_blocksums[blockIdx.x] = wsum[15];
}

__global__ void k_scan_add2() {
    __shared__ int bs[SCAN_BLOCKS];
    __shared__ int pre[SCAN_BLOCKS];
    int tid = threadIdx.x;
    if (tid < SCAN_BLOCKS) bs[tid] = g_blocksums[tid];
    __syncthreads();
    if (tid < SCAN_BLOCKS) {
        int acc = 0;
        for (int j = 0; j < SCAN_BLOCKS; j++) {
            int v = bs[j];
            if (j < tid) acc += v;
        }
        pre[tid] = acc;
    }
    __syncthreads();
    int i = blockIdx.x * 512 + tid;
    if (i < N_NODES) {
        int r = g_rowptr[i] + pre[i >> 9];
        g_rowptr[i] = r;
        g_cursor[i] = r;
    }
    if (i == N_NODES) g_rowptr[N_NODES] = N_EDGES;
}

__global__ void k_fill(const int4* __restrict__ src4, const int4* __restrict__ dst4) {
    int i = blockIdx.x * 256 + threadIdx.x;
    if (i < N_EDGES / 4) {
        int4 s = __ldg(&src4[i]);
        int4 d = __ldg(&dst4[i]);
        int p0 = atomicAdd(&g_cursor[d.x], 1);
        g_cw[p0] = make_int2(s.x, __float_as_int(g_dinv[s.x]));
        int p1 = atomicAdd(&g_cursor[d.y], 1);
        g_cw[p1] = make_int2(s.y, __float_as_int(g_dinv[s.y]));
        int p2 = atomicAdd(&g_cursor[d.z], 1);
        g_cw[p2] = make_int2(s.z, __float_as_int(g_dinv[s.z]));
        int p3 = atomicAdd(&g_cursor[d.w], 1);
        g_cw[p3] = make_int2(s.w, __float_as_int(g_dinv[s.w]));
    }
}

// ---------------- prep: split W into bf16 hi/lo, [n][k] orientation ----------------
__global__ void k_prep_w(const float* __restrict__ W1, const float* __restrict__ W2) {
    int i = blockIdx.x * 256 + threadIdx.x;
    if (i < 128 * 128) {
        int k = i >> 7, n = i & 127;
        float v = W1[i];
        __nv_bfloat16 h = __float2bfloat16(v);
        __nv_bfloat16 l = __float2bfloat16(v - __bfloat162float(h));
        g_w1hi[n * 128 + k] = h;
        g_w1lo[n * 128 + k] = l;
    } else if (i < 128 * 128 + 64 * 128) {
        int j = i - 128 * 128;
        int k = j >> 6, n = j & 63;
        float v = W2[j];
        __nv_bfloat16 h = __float2bfloat16(v);
        __nv_bfloat16 l = __float2bfloat16(v - __bfloat162float(h));
        g_w2hi[n * 128 + k] = h;
        g_w2lo[n * 128 + k] = l;
    }
}

// ---------------- bf16 mma.sync helper ----------------
__device__ __forceinline__ void mma_bf16(float& d0, float& d1, float& d2, float& d3,
                                         uint32_t a0, uint32_t a1, uint32_t a2, uint32_t a3,
                                         uint32_t b0, uint32_t b1) {
    asm volatile(
        "mma.sync.aligned.m16n8k16.row.col.f32.bf16.bf16.f32 "
        "{%0,%1,%2,%3}, {%4,%5,%6,%7}, {%8,%9}, {%0,%1,%2,%3};"
        : "+f"(d0), "+f"(d1), "+f"(d2), "+f"(d3)
        : "r"(a0), "r"(a1), "r"(a2), "r"(a3), "r"(b0), "r"(b1));
}
__device__ __forceinline__ uint32_t pack_hi2(float x, float y) {
    __nv_bfloat162 t = __halves2bfloat162(__float2bfloat16(x), __float2bfloat16(y));
    return *(uint32_t*)&t;
}
__device__ __forceinline__ uint32_t pack_lo2(float x, float y) {
    __nv_bfloat16 hx = __float2bfloat16(x), hy = __float2bfloat16(y);
    __nv_bfloat162 t = __halves2bfloat162(__float2bfloat16(x - __bfloat162float(hx)),
                                          __float2bfloat16(y - __bfloat162float(hy)));
    return *(uint32_t*)&t;
}
__device__ __forceinline__ void fma_h4(float4& acc, float w, uint2 rv) {
    float2 f0 = __half22float2(*(__half2*)&rv.x);
    float2 f1 = __half22float2(*(__half2*)&rv.y);
    acc.x = fmaf(w, f0.x, acc.x);
    acc.y = fmaf(w, f0.y, acc.y);
    acc.z = fmaf(w, f1.x, acc.z);
    acc.w = fmaf(w, f1.y, acc.w);
}

// ---------------- tensor-core GEMM via mma.sync: O = A @ W (M tile=128, K=128) ----------------
template<int NOUT>
__global__ __launch_bounds__(256) void k_mma_gemm(const float* __restrict__ Ain, int tile0) {
    extern __shared__ uint32_t smu[];
    constexpr int STR = 68;
    constexpr int WMG = (NOUT == 128) ? 2 : 4;
    constexpr int TM  = 128 / WMG;
    constexpr int MT  = TM / 16;
    constexpr int NT  = 4;

    uint32_t* As_hi = smu;
    uint32_t* As_lo = As_hi + 128 * STR;
    uint32_t* Bs_hi = As_lo + 128 * STR;
    uint32_t* Bs_lo = Bs_hi + NOUT * STR;

    const int tid = threadIdx.x;
    const int wid = tid >> 5;
    const int lane = tid & 31;
    const int g = lane >> 2;
    const int tg = lane & 3;
    const int row0 = (tile0 + blockIdx.x) * 128;

    const float* Asrc = (NOUT == 128) ? Ain : g_a1;
    const uint32_t* WhG = (NOUT == 128) ? (const uint32_t*)g_w1hi : (const uint32_t*)g_w2hi;
    const uint32_t* WlG = (NOUT == 128) ? (const uint32_t*)g_w1lo : (const uint32_t*)g_w2lo;

    const float4* A4 = (const float4*)Asrc;
    #pragma unroll 4
    for (int t = 0; t < 16; t++) {
        int i = t * 256 + tid;
        int row = i >> 5, c4 = i & 31;
        int gr = row0 + row;
        float4 v = make_float4(0.f, 0.f, 0.f, 0.f);
        if (gr < N_NODES) v = A4[(size_t)gr * 32 + c4];
        *(uint2*)&As_hi[row * STR + c4 * 2] = make_uint2(pack_hi2(v.x, v.y), pack_hi2(v.z, v.w));
        *(uint2*)&As_lo[row * STR + c4 * 2] = make_uint2(pack_lo2(v.x, v.y), pack_lo2(v.z, v.w));
    }
    for (int i = tid; i < NOUT * 64; i += 256) {
        int n = i >> 6, kp = i & 63;
        Bs_hi[n * STR + kp] = WhG[i];
        Bs_lo[n * STR + kp] = WlG[i];
    }
    __syncthreads();

    const int wm = (NOUT == 128) ? (wid & 1) : (wid & 3);
    const int wn = (NOUT == 128) ? (wid >> 1) : (wid >> 2);

    float d[MT][NT][4];
    #pragma unroll
    for (int mt = 0; mt < MT; mt++)
        #pragma unroll
        for (int nt = 0; nt < NT; nt++)
            #pragma unroll
            for (int j = 0; j < 4; j++) d[mt][nt][j] = 0.f;

    const uint32_t* Aterm[3] = {As_hi, As_hi, As_lo};
    const uint32_t* Bterm[3] = {Bs_hi, Bs_lo, Bs_hi};

    #pragma unroll
    for (int term = 0; term < 3; term++) {
        const uint32_t* Ab = Aterm[term] + (wm * TM + g) * STR;
        const uint32_t* Bb = Bterm[term] + (wn * 32 + g) * STR;
        #pragma unroll
        for (int ks = 0; ks < 8; ks++) {
            int ko = ks * 8 + tg;
            uint32_t a[MT][4], b[NT][2];
            #pragma unroll
            for (int mt = 0; mt < MT; mt++) {
                const uint32_t* Ar = Ab + mt * 16 * STR;
                a[mt][0] = Ar[ko];
                a[mt][1] = Ar[8 * STR + ko];
                a[mt][2] = Ar[ko + 4];
                a[mt][3] = Ar[8 * STR + ko + 4];
            }
            #pragma unroll
            for (int nt = 0; nt < NT; nt++) {
                const uint32_t* Br = Bb + nt * 8 * STR;
                b[nt][0] = Br[ko];
                b[nt][1] = Br[ko + 4];
            }
            #pragma unroll
            for (int mt = 0; mt < MT; mt++)
                #pragma unroll
                for (int nt = 0; nt < NT; nt++)
                    mma_bf16(d[mt][nt][0], d[mt][nt][1], d[mt][nt][2], d[mt][nt][3],
                             a[mt][0], a[mt][1], a[mt][2], a[mt][3],
                             b[nt][0], b[nt][1]);
        }
    }

    #pragma unroll
    for (int mt = 0; mt < MT; mt++) {
        int r0 = row0 + wm * TM + mt * 16 + g;
        #pragma unroll
        for (int nt = 0; nt < NT; nt++) {
            int c = wn * 32 + nt * 8 + tg * 2;
            if (NOUT == 128) {
                if (r0 < N_NODES)
                    *(__half2*)&g_h1h[(size_t)r0 * 128 + c] =
                        __floats2half2_rn(d[mt][nt][0], d[mt][nt][1]);
                if (r0 + 8 < N_NODES)
                    *(__half2*)&g_h1h[(size_t)(r0 + 8) * 128 + c] =
                        __floats2half2_rn(d[mt][nt][2], d[mt][nt][3]);
            } else {
                if (r0 < N_NODES)
                    *(__half2*)&g_h2h[(size_t)r0 * 64 + c] =
                        __floats2half2_rn(d[mt][nt][0], d[mt][nt][1]);
                if (r0 + 8 < N_NODES)
                    *(__half2*)&g_h2h[(size_t)(r0 + 8) * 64 + c] =
                        __floats2half2_rn(d[mt][nt][2], d[mt][nt][3]);
            }
        }
    }
}

// ---------------- aggregate layer 1 (fp16 gathers) + bias + relu ----------------
__global__ __launch_bounds__(256) void k_agg1(const float* __restrict__ b1,
                                              int node0, int node1) {
    int node = node0 + blockIdx.x * 8 + (threadIdx.x >> 5);
    if (node >= node1) return;
    int lane = threadIdx.x & 31;
    float di = g_dinv[node];
    const uint2* H = (const uint2*)g_h1h;
    uint2 sv = __ldg(&H[(size_t)node * 32 + lane]);
    float4 acc = make_float4(0.f, 0.f, 0.f, 0.f);
    fma_h4(acc, di, sv);
    int beg = g_rowptr[node];
    int end = g_rowptr[node + 1];
    #pragma unroll 8
    for (int e = beg; e < end; e++) {
        int2 cw = __ldg(&g_cw[e]);
        float w = __int_as_float(cw.y);
        uint2 hv = __ldg(&H[(size_t)cw.x * 32 + lane]);
        fma_h4(acc, w, hv);
    }
    float4 bv = ((const float4*)b1)[lane];
    float4 out;
    out.x = fmaxf(fmaf(acc.x, di, bv.x), 0.f);
    out.y = fmaxf(fmaf(acc.y, di, bv.y), 0.f);
    out.z = fmaxf(fmaf(acc.z, di, bv.z), 0.f);
    out.w = fmaxf(fmaf(acc.w, di, bv.w), 0.f);
    ((float4*)g_a1)[(size_t)node * 32 + lane] = out;
}

// ---------------- aggregate layer 2 (fp16 gathers) + bias + log_softmax ----------------
__global__ __launch_bounds__(256) void k_agg2(const float* __restrict__ b2,
                                              float* __restrict__ out) {
    int node = blockIdx.x * 8 + (threadIdx.x >> 5);
    if (node >= N_NODES) return;
    int lane = threadIdx.x & 31;
    float di = g_dinv[node];
    const __half2* H = (const __half2*)g_h2h;
    float2 self = __half22float2(__ldg(&H[(size_t)node * 32 + lane]));
    float2 acc = make_float2(di * self.x, di * self.y);
    int beg = g_rowptr[node];
    int end = g_rowptr[node + 1];
    #pragma unroll 8
    for (int e = beg; e < end; e++) {
        int2 cw = __ldg(&g_cw[e]);
        float w = __int_as_float(cw.y);
        float2 hv = __half22float2(__ldg(&H[(size_t)cw.x * 32 + lane]));
        acc.x = fmaf(w, hv.x, acc.x);
        acc.y = fmaf(w, hv.y, acc.y);
    }
    float2 bv = ((const float2*)b2)[lane];
    float vx = fmaf(acc.x, di, bv.x);
    float vy = fmaf(acc.y, di, bv.y);

    float m = fmaxf(vx, vy);
    #pragma unroll
    for (int o = 16; o > 0; o >>= 1) m = fmaxf(m, __shfl_xor_sync(0xffffffffu, m, o));
    float s = expf(vx - m) + expf(vy - m);
    #pragma unroll
    for (int o = 16; o > 0; o >>= 1) s += __shfl_xor_sync(0xffffffffu, s, o);
    float lse = m + logf(s);
    ((float2*)out)[(size_t)node * 32 + lane] = make_float2(vx - lse, vy - lse);
}

// ---------------- launch ----------------
extern "C" void kernel_launch(void* const* d_in, const int* in_sizes, int n_in,
                              void* d_out, int out_size) {
    const float* x  = (const float*)d_in[0];
    const int*   ei = (const int*)d_in[1];
    const float* W1 = (const float*)d_in[2];
    const float* b1 = (const float*)d_in[3];
    const float* W2 = (const float*)d_in[4];
    const float* b2 = (const float*)d_in[5];
    float* out = (float*)d_out;

    const int4* src4 = (const int4*)ei;
    const int4* dst4 = (const int4*)(ei + N_EDGES);

    const int SMEM1 = (2 * 128 * 68 + 2 * 128 * 68) * 4;
    const int SMEM2 = (2 * 128 * 68 + 2 * 64 * 68) * 4;
    cudaFuncSetAttribute(k_mma_gemm<128>, cudaFuncAttributeMaxDynamicSharedMemorySize, SMEM1);
    cudaFuncSetAttribute(k_mma_gemm<64>,  cudaFuncAttributeMaxDynamicSharedMemorySize, SMEM2);

    void* degptr = nullptr;
    cudaGetSymbolAddress(&degptr, g_deg);

    cudaStream_t s1;
    cudaStreamCreateWithFlags(&s1, cudaStreamNonBlocking);
    cudaEvent_t evFork, evG1, evG2;
    cudaEvent_t evA[CHUNKS];
    cudaEventCreateWithFlags(&evFork, cudaEventDisableTiming);
    cudaEventCreateWithFlags(&evG1, cudaEventDisableTiming);
    cudaEventCreateWithFlags(&evG2, cudaEventDisableTiming);
    for (int c = 0; c < CHUNKS; c++) cudaEventCreateWithFlags(&evA[c], cudaEventDisableTiming);

    cudaEventRecord(evFork, 0);
    cudaStreamWaitEvent(s1, evFork, 0);

    // side stream: weight prep + GEMM1 (independent of graph structure)
    k_prep_w<<<(128 * 128 + 64 * 128 + 255) / 256, 256, 0, s1>>>(W1, W2);
    k_mma_gemm<128><<<NTILES, 256, SMEM1, s1>>>(x, 0);
    cudaEventRecord(evG1, s1);

    // main stream: CSR build
    cudaMemsetAsync(degptr, 0, N_NODES * sizeof(int));
    k_count<<<(N_EDGES / 4 + 255) / 256, 256>>>(dst4);
    k_scan_part<<<SCAN_BLOCKS, 512>>>();
    k_scan_add2<<<(N_NODES + 512) / 512, 512>>>();
    k_fill<<<(N_EDGES / 4 + 255) / 256, 256>>>(src4, dst4);

    cudaStreamWaitEvent(0, evG1, 0);

    // pipelined agg1 (main) -> gemm2 chunk (side)
    for (int c = 0; c < CHUNKS; c++) {
        int t0 = c * TILES_PER_CHUNK;
        int t1 = (c == CHUNKS - 1) ? NTILES : (c + 1) * TILES_PER_CHUNK;
        int n0 = t0 * 128;
        int n1 = (t1 * 128 < N_NODES) ? t1 * 128 : N_NODES;
        int blocks = (n1 - n0 + 7) / 8;
        k_agg1<<<blocks, 256>>>(b1, n0, n1);
        cudaEventRecord(evA[c], 0);
        cudaStreamWaitEvent(s1, evA[c], 0);
        k_mma_gemm<64><<<t1 - t0, 256, SMEM2, s1>>>(nullptr, t0);
    }
    cudaEventRecord(evG2, s1);
    cudaStreamWaitEvent(0, evG2, 0);

    k_agg2<<<(N_NODES + 7) / 8, 256>>>(b2, out);
}

// round 9
// speedup vs baseline: 1.7194x; 1.1088x over previous
#include <cuda_runtime.h>
#include <cuda_bf16.h>
#include <cuda_fp16.h>
#include <cstdint>
#include <math.h>

#define N_NODES 100000
#define N_EDGES 1600000
#define SCAN_BLOCKS 256
#define NTILES 782           // ceil(100000/128)
#define CHUNKS 4
#define TILES_PER_CHUNK 196

// ---------------- scratch ----------------
__device__ int   g_deg[N_NODES];
__device__ float g_dinv[N_NODES];
__device__ int   g_rowptr[N_NODES + 1];
__device__ int   g_cursor[N_NODES];
__device__ int2  g_cw[N_EDGES];
__device__ int   g_blocksums[SCAN_BLOCKS];
__device__ __align__(16) __half g_h1h[(size_t)N_NODES * 128];
__device__ __align__(16) float  g_a1[(size_t)N_NODES * 128];
__device__ __align__(16) __half g_h2h[(size_t)N_NODES * 64];
__device__ __align__(16) __nv_bfloat16 g_w1hi[128 * 128];
__device__ __align__(16) __nv_bfloat16 g_w1lo[128 * 128];
__device__ __align__(16) __nv_bfloat16 g_w2hi[64 * 128];
__device__ __align__(16) __nv_bfloat16 g_w2lo[64 * 128];

// ---------------- degree / scan / CSR ----------------
__global__ void k_count(const int4* __restrict__ dst4) {
    int i = blockIdx.x * 256 + threadIdx.x;
    if (i < N_EDGES / 4) {
        int4 d = __ldg(&dst4[i]);
        atomicAdd(&g_deg[d.x], 1);
        atomicAdd(&g_deg[d.y], 1);
        atomicAdd(&g_deg[d.z], 1);
        atomicAdd(&g_deg[d.w], 1);
    }
}

__global__ void k_scan_part() {
    __shared__ int wsum[16];
    int tid = threadIdx.x;
    int lane = tid & 31, wid = tid >> 5;
    int i = blockIdx.x * 512 + tid;
    int c = 0;
    if (i < N_NODES) {
        int d = g_deg[i];
        g_dinv[i] = rsqrtf((float)(d + 1));
        c = d;
    }
    int v = c;
    #pragma unroll
    for (int o = 1; o < 32; o <<= 1) {
        int t = __shfl_up_sync(0xffffffffu, v, o);
        if (lane >= o) v += t;
    }
    if (lane == 31) wsum[wid] = v;
    __syncthreads();
    if (wid == 0) {
        int s = (lane < 16) ? wsum[lane] : 0;
        #pragma unroll
        for (int o = 1; o < 16; o <<= 1) {
            int t = __shfl_up_sync(0xffffffffu, s, o);
            if (lane >= o) s += t;
        }
        if (lane < 16) wsum[lane] = s;
    }
    __syncthreads();
    int off = (wid > 0) ? wsum[wid - 1] : 0;
    if (i < N_NODES) g_rowptr[i] = off + v - c;
    if (tid == 511) g_blocksums[blockIdx.x] = wsum[15];
}

__global__ void k_scan_add2() {
    __shared__ int bs[SCAN_BLOCKS];
    __shared__ int pre[SCAN_BLOCKS];
    int tid = threadIdx.x;
    if (tid < SCAN_BLOCKS) bs[tid] = g_blocksums[tid];
    __syncthreads();
    if (tid < SCAN_BLOCKS) {
        int acc = 0;
        for (int j = 0; j < SCAN_BLOCKS; j++) {
            int v = bs[j];
            if (j < tid) acc += v;
        }
        pre[tid] = acc;
    }
    __syncthreads();
    int i = blockIdx.x * 512 + tid;
    if (i < N_NODES) {
        int r = g_rowptr[i] + pre[i >> 9];
        g_rowptr[i] = r;
        g_cursor[i] = r;
    }
    if (i == N_NODES) g_rowptr[N_NODES] = N_EDGES;
}

__global__ void k_fill(const int4* __restrict__ src4, const int4* __restrict__ dst4) {
    int i = blockIdx.x * 256 + threadIdx.x;
    if (i < N_EDGES / 4) {
        int4 s = __ldg(&src4[i]);
        int4 d = __ldg(&dst4[i]);
        int p0 = atomicAdd(&g_cursor[d.x], 1);
        g_cw[p0] = make_int2(s.x, __float_as_int(g_dinv[s.x]));
        int p1 = atomicAdd(&g_cursor[d.y], 1);
        g_cw[p1] = make_int2(s.y, __float_as_int(g_dinv[s.y]));
        int p2 = atomicAdd(&g_cursor[d.z], 1);
        g_cw[p2] = make_int2(s.z, __float_as_int(g_dinv[s.z]));
        int p3 = atomicAdd(&g_cursor[d.w], 1);
        g_cw[p3] = make_int2(s.w, __float_as_int(g_dinv[s.w]));
    }
}

// ---------------- prep ----------------
__global__ void k_prep_w(const float* __restrict__ W1, const float* __restrict__ W2) {
    int i = blockIdx.x * 256 + threadIdx.x;
    if (i < 128 * 128) {
        int k = i >> 7, n = i & 127;
        float v = W1[i];
        __nv_bfloat16 h = __float2bfloat16(v);
        __nv_bfloat16 l = __float2bfloat16(v - __bfloat162float(h));
        g_w1hi[n * 128 + k] = h;
        g_w1lo[n * 128 + k] = l;
    } else if (i < 128 * 128 + 64 * 128) {
        int j = i - 128 * 128;
        int k = j >> 6, n = j & 63;
        float v = W2[j];
        __nv_bfloat16 h = __float2bfloat16(v);
        __nv_bfloat16 l = __float2bfloat16(v - __bfloat162float(h));
        g_w2hi[n * 128 + k] = h;
        g_w2lo[n * 128 + k] = l;
    }
}

// ---------------- helpers ----------------
__device__ __forceinline__ void mma_bf16(float& d0, float& d1, float& d2, float& d3,
                                         uint32_t a0, uint32_t a1, uint32_t a2, uint32_t a3,
                                         uint32_t b0, uint32_t b1) {
    asm volatile(
        "mma.sync.aligned.m16n8k16.row.col.f32.bf16.bf16.f32 "
        "{%0,%1,%2,%3}, {%4,%5,%6,%7}, {%8,%9}, {%0,%1,%2,%3};"
        : "+f"(d0), "+f"(d1), "+f"(d2), "+f"(d3)
        : "r"(a0), "r"(a1), "r"(a2), "r"(a3), "r"(b0), "r"(b1));
}
__device__ __forceinline__ uint32_t pack_hi2(float x, float y) {
    __nv_bfloat162 t = __halves2bfloat162(__float2bfloat16(x), __float2bfloat16(y));
    return *(uint32_t*)&t;
}
__device__ __forceinline__ uint32_t pack_lo2(float x, float y) {
    __nv_bfloat16 hx = __float2bfloat16(x), hy = __float2bfloat16(y);
    __nv_bfloat162 t = __halves2bfloat162(__float2bfloat16(x - __bfloat162float(hx)),
                                          __float2bfloat16(y - __bfloat162float(hy)));
    return *(uint32_t*)&t;
}
__device__ __forceinline__ void fma_h8(float* acc, float w, uint4 rv) {
    float2 f0 = __half22float2(*(__half2*)&rv.x);
    float2 f1 = __half22float2(*(__half2*)&rv.y);
    float2 f2 = __half22float2(*(__half2*)&rv.z);
    float2 f3 = __half22float2(*(__half2*)&rv.w);
    acc[0] = fmaf(w, f0.x, acc[0]);
    acc[1] = fmaf(w, f0.y, acc[1]);
    acc[2] = fmaf(w, f1.x, acc[2]);
    acc[3] = fmaf(w, f1.y, acc[3]);
    acc[4] = fmaf(w, f2.x, acc[4]);
    acc[5] = fmaf(w, f2.y, acc[5]);
    acc[6] = fmaf(w, f3.x, acc[6]);
    acc[7] = fmaf(w, f3.y, acc[7]);
}

// ---------------- GEMM (K split into two 64 halves; A smem halved) ----------------
template<int NOUT>
__global__ __launch_bounds__(256) void k_mma_gemm(const float* __restrict__ Ain, int tile0) {
    extern __shared__ uint32_t smu[];
    constexpr int STRA = 36;   // u32 per 64-K half row (conflict-free: 36 mod 32 = 4)
    constexpr int STRB = 68;   // u32 per 128-K row
    constexpr int WMG = (NOUT == 128) ? 2 : 4;
    constexpr int TM  = 128 / WMG;
    constexpr int MT  = TM / 16;
    constexpr int NT  = 4;

    uint32_t* As_hi = smu;                         // 128 * 36
    uint32_t* As_lo = As_hi + 128 * STRA;
    uint32_t* Bs_hi = As_lo + 128 * STRA;          // NOUT * 68
    uint32_t* Bs_lo = Bs_hi + NOUT * STRB;

    const int tid = threadIdx.x;
    const int wid = tid >> 5;
    const int lane = tid & 31;
    const int g = lane >> 2;
    const int tg = lane & 3;
    const int row0 = (tile0 + blockIdx.x) * 128;

    const float* Asrc = (NOUT == 128) ? Ain : g_a1;
    const uint32_t* WhG = (NOUT == 128) ? (const uint32_t*)g_w1hi : (const uint32_t*)g_w2hi;
    const uint32_t* WlG = (NOUT == 128) ? (const uint32_t*)g_w1lo : (const uint32_t*)g_w2lo;

    // stage full B once
    for (int i = tid; i < NOUT * 64; i += 256) {
        int n = i >> 6, kp = i & 63;
        Bs_hi[n * STRB + kp] = WhG[i];
        Bs_lo[n * STRB + kp] = WlG[i];
    }

    const int wm = (NOUT == 128) ? (wid & 1) : (wid & 3);
    const int wn = (NOUT == 128) ? (wid >> 1) : (wid >> 2);

    float d[MT][NT][4];
    #pragma unroll
    for (int mt = 0; mt < MT; mt++)
        #pragma unroll
        for (int nt = 0; nt < NT; nt++)
            #pragma unroll
            for (int j = 0; j < 4; j++) d[mt][nt][j] = 0.f;

    const float4* A4 = (const float4*)Asrc;
    const uint32_t* Aterm[3] = {As_hi, As_hi, As_lo};
    const uint32_t* Bterm[3] = {Bs_hi, Bs_lo, Bs_hi};

    #pragma unroll
    for (int h = 0; h < 2; h++) {
        __syncthreads();
        // stage A half: 128 rows x 16 float4
        #pragma unroll
        for (int t = 0; t < 8; t++) {
            int i = t * 256 + tid;
            int row = i >> 4, c4l = i & 15;
            int gr = row0 + row;
            float4 v = make_float4(0.f, 0.f, 0.f, 0.f);
            if (gr < N_NODES) v = A4[(size_t)gr * 32 + h * 16 + c4l];
            *(uint2*)&As_hi[row * STRA + c4l * 2] = make_uint2(pack_hi2(v.x, v.y), pack_hi2(v.z, v.w));
            *(uint2*)&As_lo[row * STRA + c4l * 2] = make_uint2(pack_lo2(v.x, v.y), pack_lo2(v.z, v.w));
        }
        __syncthreads();
        #pragma unroll
        for (int term = 0; term < 3; term++) {
            const uint32_t* Ab = Aterm[term] + (wm * TM + g) * STRA;
            const uint32_t* Bb = Bterm[term] + (wn * 32 + g) * STRB;
            #pragma unroll
            for (int ks = 0; ks < 4; ks++) {
                int koA = ks * 8 + tg;
                int koB = (h * 4 + ks) * 8 + tg;
                uint32_t a[MT][4], b[NT][2];
                #pragma unroll
                for (int mt = 0; mt < MT; mt++) {
                    const uint32_t* Ar = Ab + mt * 16 * STRA;
                    a[mt][0] = Ar[koA];
                    a[mt][1] = Ar[8 * STRA + koA];
                    a[mt][2] = Ar[koA + 4];
                    a[mt][3] = Ar[8 * STRA + koA + 4];
                }
                #pragma unroll
                for (int nt = 0; nt < NT; nt++) {
                    const uint32_t* Br = Bb + nt * 8 * STRB;
                    b[nt][0] = Br[koB];
                    b[nt][1] = Br[koB + 4];
                }
                #pragma unroll
                for (int mt = 0; mt < MT; mt++)
                    #pragma unroll
                    for (int nt = 0; nt < NT; nt++)
                        mma_bf16(d[mt][nt][0], d[mt][nt][1], d[mt][nt][2], d[mt][nt][3],
                                 a[mt][0], a[mt][1], a[mt][2], a[mt][3],
                                 b[nt][0], b[nt][1]);
            }
        }
    }

    #pragma unroll
    for (int mt = 0; mt < MT; mt++) {
        int r0 = row0 + wm * TM + mt * 16 + g;
        #pragma unroll
        for (int nt = 0; nt < NT; nt++) {
            int c = wn * 32 + nt * 8 + tg * 2;
            if (NOUT == 128) {
                if (r0 < N_NODES)
                    *(__half2*)&g_h1h[(size_t)r0 * 128 + c] =
                        __floats2half2_rn(d[mt][nt][0], d[mt][nt][1]);
                if (r0 + 8 < N_NODES)
                    *(__half2*)&g_h1h[(size_t)(r0 + 8) * 128 + c] =
                        __floats2half2_rn(d[mt][nt][2], d[mt][nt][3]);
            } else {
                if (r0 < N_NODES)
                    *(__half2*)&g_h2h[(size_t)r0 * 64 + c] =
                        __floats2half2_rn(d[mt][nt][0], d[mt][nt][1]);
                if (r0 + 8 < N_NODES)
                    *(__half2*)&g_h2h[(size_t)(r0 + 8) * 64 + c] =
                        __floats2half2_rn(d[mt][nt][2], d[mt][nt][3]);
            }
        }
    }
}

// ---------------- agg1: half-warp per node (16 lanes x uint4 = 256B row) ----------------
__global__ __launch_bounds__(256) void k_agg1(const float* __restrict__ b1,
                                              int node0, int node1) {
    int node = node0 + blockIdx.x * 16 + (threadIdx.x >> 4);
    if (node >= node1) return;   // chunk sizes are multiples of 16 -> no partial half-warps
    int hl = threadIdx.x & 15;
    float di = g_dinv[node];
    const uint4* H = (const uint4*)g_h1h;   // 16 uint4 per row
    float acc[8] = {0.f, 0.f, 0.f, 0.f, 0.f, 0.f, 0.f, 0.f};
    uint4 sv = __ldg(&H[(size_t)node * 16 + hl]);
    fma_h8(acc, di, sv);
    int beg = g_rowptr[node];
    int end = g_rowptr[node + 1];
    #pragma unroll 4
    for (int e = beg; e < end; e++) {
        int2 cw = __ldg(&g_cw[e]);
        float w = __int_as_float(cw.y);
        uint4 hv = __ldg(&H[(size_t)cw.x * 16 + hl]);
        fma_h8(acc, w, hv);
    }
    float4 bv0 = ((const float4*)b1)[hl * 2];
    float4 bv1 = ((const float4*)b1)[hl * 2 + 1];
    float4 o0, o1;
    o0.x = fmaxf(fmaf(acc[0], di, bv0.x), 0.f);
    o0.y = fmaxf(fmaf(acc[1], di, bv0.y), 0.f);
    o0.z = fmaxf(fmaf(acc[2], di, bv0.z), 0.f);
    o0.w = fmaxf(fmaf(acc[3], di, bv0.w), 0.f);
    o1.x = fmaxf(fmaf(acc[4], di, bv1.x), 0.f);
    o1.y = fmaxf(fmaf(acc[5], di, bv1.y), 0.f);
    o1.z = fmaxf(fmaf(acc[6], di, bv1.z), 0.f);
    o1.w = fmaxf(fmaf(acc[7], di, bv1.w), 0.f);
    ((float4*)g_a1)[(size_t)node * 32 + hl * 2]     = o0;
    ((float4*)g_a1)[(size_t)node * 32 + hl * 2 + 1] = o1;
}

// ---------------- agg2: half-warp per node (16 lanes x uint2 = 128B row) ----------------
__global__ __launch_bounds__(256) void k_agg2(const float* __restrict__ b2,
                                              float* __restrict__ out) {
    int node = blockIdx.x * 16 + (threadIdx.x >> 4);   // grid exact: 6250*16 = 100000
    int hl = threadIdx.x & 15;
    float di = g_dinv[node];
    const uint2* H = (const uint2*)g_h2h;   // 16 uint2 per row
    uint2 sv = __ldg(&H[(size_t)node * 16 + hl]);
    float acc[4] = {0.f, 0.f, 0.f, 0.f};
    {
        float2 f0 = __half22float2(*(__half2*)&sv.x);
        float2 f1 = __half22float2(*(__half2*)&sv.y);
        acc[0] = di * f0.x; acc[1] = di * f0.y;
        acc[2] = di * f1.x; acc[3] = di * f1.y;
    }
    int beg = g_rowptr[node];
    int end = g_rowptr[node + 1];
    #pragma unroll 4
    for (int e = beg; e < end; e++) {
        int2 cw = __ldg(&g_cw[e]);
        float w = __int_as_float(cw.y);
        uint2 hv = __ldg(&H[(size_t)cw.x * 16 + hl]);
        float2 f0 = __half22float2(*(__half2*)&hv.x);
        float2 f1 = __half22float2(*(__half2*)&hv.y);
        acc[0] = fmaf(w, f0.x, acc[0]);
        acc[1] = fmaf(w, f0.y, acc[1]);
        acc[2] = fmaf(w, f1.x, acc[2]);
        acc[3] = fmaf(w, f1.y, acc[3]);
    }
    float4 bv = ((const float4*)b2)[hl];
    float v0 = fmaf(acc[0], di, bv.x);
    float v1 = fmaf(acc[1], di, bv.y);
    float v2 = fmaf(acc[2], di, bv.z);
    float v3 = fmaf(acc[3], di, bv.w);

    // log_softmax over 64 values in the half-warp (16 lanes x 4)
    float m = fmaxf(fmaxf(v0, v1), fmaxf(v2, v3));
    #pragma unroll
    for (int o = 8; o > 0; o >>= 1) m = fmaxf(m, __shfl_xor_sync(0xffffffffu, m, o));
    float s = expf(v0 - m) + expf(v1 - m) + expf(v2 - m) + expf(v3 - m);
    #pragma unroll
    for (int o = 8; o > 0; o >>= 1) s += __shfl_xor_sync(0xffffffffu, s, o);
    float lse = m + logf(s);
    ((float4*)out)[(size_t)node * 16 + hl] =
        make_float4(v0 - lse, v1 - lse, v2 - lse, v3 - lse);
}

// ---------------- launch ----------------
extern "C" void kernel_launch(void* const* d_in, const int* in_sizes, int n_in,
                              void* d_out, int out_size) {
    const float* x  = (const float*)d_in[0];
    const int*   ei = (const int*)d_in[1];
    const float* W1 = (const float*)d_in[2];
    const float* b1 = (const float*)d_in[3];
    const float* W2 = (const float*)d_in[4];
    const float* b2 = (const float*)d_in[5];
    float* out = (float*)d_out;

    const int4* src4 = (const int4*)ei;
    const int4* dst4 = (const int4*)(ei + N_EDGES);

    const int SMEM1 = (2 * 128 * 36 + 2 * 128 * 68) * 4;  // 106496 -> 2 blocks/SM
    const int SMEM2 = (2 * 128 * 36 + 2 * 64 * 68) * 4;   //  71680 -> 3 blocks/SM
    cudaFuncSetAttribute(k_mma_gemm<128>, cudaFuncAttributeMaxDynamicSharedMemorySize, SMEM1);
    cudaFuncSetAttribute(k_mma_gemm<64>,  cudaFuncAttributeMaxDynamicSharedMemorySize, SMEM2);

    void* degptr = nullptr;
    cudaGetSymbolAddress(&degptr, g_deg);

    cudaStream_t s1;
    cudaStreamCreateWithFlags(&s1, cudaStreamNonBlocking);
    cudaEvent_t evFork, evG1, evG2;
    cudaEvent_t evA[CHUNKS];
    cudaEventCreateWithFlags(&evFork, cudaEventDisableTiming);
    cudaEventCreateWithFlags(&evG1, cudaEventDisableTiming);
    cudaEventCreateWithFlags(&evG2, cudaEventDisableTiming);
    for (int c = 0; c < CHUNKS; c++) cudaEventCreateWithFlags(&evA[c], cudaEventDisableTiming);

    cudaEventRecord(evFork, 0);
    cudaStreamWaitEvent(s1, evFork, 0);

    // side stream: weight prep + GEMM1
    k_prep_w<<<(128 * 128 + 64 * 128 + 255) / 256, 256, 0, s1>>>(W1, W2);
    k_mma_gemm<128><<<NTILES, 256, SMEM1, s1>>>(x, 0);
    cudaEventRecord(evG1, s1);

    // main stream: CSR build
    cudaMemsetAsync(degptr, 0, N_NODES * sizeof(int));
    k_count<<<(N_EDGES / 4 + 255) / 256, 256>>>(dst4);
    k_scan_part<<<SCAN_BLOCKS, 512>>>();
    k_scan_add2<<<(N_NODES + 512) / 512, 512>>>();
    k_fill<<<(N_EDGES / 4 + 255) / 256, 256>>>(src4, dst4);

    cudaStreamWaitEvent(0, evG1, 0);

    // pipelined agg1 (main) -> gemm2 chunk (side)
    for (int c = 0; c < CHUNKS; c++) {
        int t0 = c * TILES_PER_CHUNK;
        int t1 = (c == CHUNKS - 1) ? NTILES : (c + 1) * TILES_PER_CHUNK;
        int n0 = t0 * 128;
        int n1 = (t1 * 128 < N_NODES) ? t1 * 128 : N_NODES;
        int blocks = (n1 - n0 + 15) / 16;
        k_agg1<<<blocks, 256>>>(b1, n0, n1);
        cudaEventRecord(evA[c], 0);
        cudaStreamWaitEvent(s1, evA[c], 0);
        k_mma_gemm<64><<<t1 - t0, 256, SMEM2, s1>>>(nullptr, t0);
    }
    cudaEventRecord(evG2, s1);
    cudaStreamWaitEvent(0, evG2, 0);

    k_agg2<<<N_NODES / 16, 256>>>(b2, out);
}

// round 10
// speedup vs baseline: 1.8754x; 1.0907x over previous
#include <cuda_runtime.h>
#include <cuda_bf16.h>
#include <cuda_fp16.h>
#include <cstdint>
#include <math.h>

#define N_NODES 100000
#define N_EDGES 1600000
#define SCAN_BLOCKS 256
#define NTILES 782           // ceil(100000/128)
#define CHUNKS 4
#define TILES_PER_CHUNK 196

// ---------------- scratch ----------------
__device__ int   g_deg[N_NODES];
__device__ float g_dinv[N_NODES];
__device__ int   g_rowptr[N_NODES + 1];
__device__ int   g_cursor[N_NODES];
__device__ int2  g_cw[N_EDGES];
__device__ int   g_blocksums[SCAN_BLOCKS];
__device__ __align__(16) __half g_h1h[(size_t)N_NODES * 128];
__device__ __align__(16) __half g_a1h[(size_t)N_NODES * 128];   // fp16 a1
__device__ __align__(16) __half g_h2h[(size_t)N_NODES * 64];
__device__ __align__(16) __nv_bfloat16 g_w1hi[128 * 128];
__device__ __align__(16) __nv_bfloat16 g_w1lo[128 * 128];
__device__ __align__(16) __nv_bfloat16 g_w2hi[64 * 128];
__device__ __align__(16) __nv_bfloat16 g_w2lo[64 * 128];

// ---------------- degree / scan / CSR ----------------
__global__ void k_count(const int4* __restrict__ dst4) {
    int i = blockIdx.x * 256 + threadIdx.x;
    if (i < N_EDGES / 4) {
        int4 d = __ldg(&dst4[i]);
        atomicAdd(&g_deg[d.x], 1);
        atomicAdd(&g_deg[d.y], 1);
        atomicAdd(&g_deg[d.z], 1);
        atomicAdd(&g_deg[d.w], 1);
    }
}

__global__ void k_scan_part() {
    __shared__ int wsum[16];
    int tid = threadIdx.x;
    int lane = tid & 31, wid = tid >> 5;
    int i = blockIdx.x * 512 + tid;
    int c = 0;
    if (i < N_NODES) {
        int d = g_deg[i];
        g_dinv[i] = rsqrtf((float)(d + 1));
        c = d;
    }
    int v = c;
    #pragma unroll
    for (int o = 1; o < 32; o <<= 1) {
        int t = __shfl_up_sync(0xffffffffu, v, o);
        if (lane >= o) v += t;
    }
    if (lane == 31) wsum[wid] = v;
    __syncthreads();
    if (wid == 0) {
        int s = (lane < 16) ? wsum[lane] : 0;
        #pragma unroll
        for (int o = 1; o < 16; o <<= 1) {
            int t = __shfl_up_sync(0xffffffffu, s, o);
            if (lane >= o) s += t;
        }
        if (lane < 16) wsum[lane] = s;
    }
    __syncthreads();
    int off = (wid > 0) ? wsum[wid - 1] : 0;
    if (i < N_NODES) g_rowptr[i] = off + v - c;
    if (tid == 511) g_blocksums[blockIdx.x] = wsum[15];
}

__global__ void k_scan_add2() {
    __shared__ int bs[SCAN_BLOCKS];
    __shared__ int pre[SCAN_BLOCKS];
    int tid = threadIdx.x;
    if (tid < SCAN_BLOCKS) bs[tid] = g_blocksums[tid];
    __syncthreads();
    if (tid < SCAN_BLOCKS) {
        int acc = 0;
        for (int j = 0; j < SCAN_BLOCKS; j++) {
            int v = bs[j];
            if (j < tid) acc += v;
        }
        pre[tid] = acc;
    }
    __syncthreads();
    int i = blockIdx.x * 512 + tid;
    if (i < N_NODES) {
        int r = g_rowptr[i] + pre[i >> 9];
        g_rowptr[i] = r;
        g_cursor[i] = r;
    }
    if (i == N_NODES) g_rowptr[N_NODES] = N_EDGES;
}

__global__ void k_fill(const int4* __restrict__ src4, const int4* __restrict__ dst4) {
    int i = blockIdx.x * 256 + threadIdx.x;
    if (i < N_EDGES / 4) {
        int4 s = __ldg(&src4[i]);
        int4 d = __ldg(&dst4[i]);
        int p0 = atomicAdd(&g_cursor[d.x], 1);
        g_cw[p0] = make_int2(s.x, __float_as_int(g_dinv[s.x]));
        int p1 = atomicAdd(&g_cursor[d.y], 1);
        g_cw[p1] = make_int2(s.y, __float_as_int(g_dinv[s.y]));
        int p2 = atomicAdd(&g_cursor[d.z], 1);
        g_cw[p2] = make_int2(s.z, __float_as_int(g_dinv[s.z]));
        int p3 = atomicAdd(&g_cursor[d.w], 1);
        g_cw[p3] = make_int2(s.w, __float_as_int(g_dinv[s.w]));
    }
}

// ---------------- prep ----------------
__global__ void k_prep_w(const float* __restrict__ W1, const float* __restrict__ W2) {
    int i = blockIdx.x * 256 + threadIdx.x;
    if (i < 128 * 128) {
        int k = i >> 7, n = i & 127;
        float v = W1[i];
        __nv_bfloat16 h = __float2bfloat16(v);
        __nv_bfloat16 l = __float2bfloat16(v - __bfloat162float(h));
        g_w1hi[n * 128 + k] = h;
        g_w1lo[n * 128 + k] = l;
    } else if (i < 128 * 128 + 64 * 128) {
        int j = i - 128 * 128;
        int k = j >> 6, n = j & 63;
        float v = W2[j];
        __nv_bfloat16 h = __float2bfloat16(v);
        __nv_bfloat16 l = __float2bfloat16(v - __bfloat162float(h));
        g_w2hi[n * 128 + k] = h;
        g_w2lo[n * 128 + k] = l;
    }
}

// ---------------- helpers ----------------
__device__ __forceinline__ void mma_bf16(float& d0, float& d1, float& d2, float& d3,
                                         uint32_t a0, uint32_t a1, uint32_t a2, uint32_t a3,
                                         uint32_t b0, uint32_t b1) {
    asm volatile(
        "mma.sync.aligned.m16n8k16.row.col.f32.bf16.bf16.f32 "
        "{%0,%1,%2,%3}, {%4,%5,%6,%7}, {%8,%9}, {%0,%1,%2,%3};"
        : "+f"(d0), "+f"(d1), "+f"(d2), "+f"(d3)
        : "r"(a0), "r"(a1), "r"(a2), "r"(a3), "r"(b0), "r"(b1));
}
__device__ __forceinline__ uint32_t pack_hi2(float x, float y) {
    __nv_bfloat162 t = __halves2bfloat162(__float2bfloat16(x), __float2bfloat16(y));
    return *(uint32_t*)&t;
}
__device__ __forceinline__ uint32_t pack_lo2(float x, float y) {
    __nv_bfloat16 hx = __float2bfloat16(x), hy = __float2bfloat16(y);
    __nv_bfloat162 t = __halves2bfloat162(__float2bfloat16(x - __bfloat162float(hx)),
                                          __float2bfloat16(y - __bfloat162float(hy)));
    return *(uint32_t*)&t;
}
__device__ __forceinline__ void fma_h8(float* acc, float w, uint4 rv) {
    float2 f0 = __half22float2(*(__half2*)&rv.x);
    float2 f1 = __half22float2(*(__half2*)&rv.y);
    float2 f2 = __half22float2(*(__half2*)&rv.z);
    float2 f3 = __half22float2(*(__half2*)&rv.w);
    acc[0] = fmaf(w, f0.x, acc[0]);
    acc[1] = fmaf(w, f0.y, acc[1]);
    acc[2] = fmaf(w, f1.x, acc[2]);
    acc[3] = fmaf(w, f1.y, acc[3]);
    acc[4] = fmaf(w, f2.x, acc[4]);
    acc[5] = fmaf(w, f2.y, acc[5]);
    acc[6] = fmaf(w, f3.x, acc[6]);
    acc[7] = fmaf(w, f3.y, acc[7]);
}

// ---------------- GEMM (K split into two 64 halves; A smem halved) ----------------
template<int NOUT>
__global__ __launch_bounds__(256) void k_mma_gemm(const float* __restrict__ Ain, int tile0) {
    extern __shared__ uint32_t smu[];
    constexpr int STRA = 36;
    constexpr int STRB = 68;
    constexpr int WMG = (NOUT == 128) ? 2 : 4;
    constexpr int TM  = 128 / WMG;
    constexpr int MT  = TM / 16;
    constexpr int NT  = 4;

    uint32_t* As_hi = smu;
    uint32_t* As_lo = As_hi + 128 * STRA;
    uint32_t* Bs_hi = As_lo + 128 * STRA;
    uint32_t* Bs_lo = Bs_hi + NOUT * STRB;

    const int tid = threadIdx.x;
    const int wid = tid >> 5;
    const int lane = tid & 31;
    const int g = lane >> 2;
    const int tg = lane & 3;
    const int row0 = (tile0 + blockIdx.x) * 128;

    const uint32_t* WhG = (NOUT == 128) ? (const uint32_t*)g_w1hi : (const uint32_t*)g_w2hi;
    const uint32_t* WlG = (NOUT == 128) ? (const uint32_t*)g_w1lo : (const uint32_t*)g_w2lo;

    for (int i = tid; i < NOUT * 64; i += 256) {
        int n = i >> 6, kp = i & 63;
        Bs_hi[n * STRB + kp] = WhG[i];
        Bs_lo[n * STRB + kp] = WlG[i];
    }

    const int wm = (NOUT == 128) ? (wid & 1) : (wid & 3);
    const int wn = (NOUT == 128) ? (wid >> 1) : (wid >> 2);

    float d[MT][NT][4];
    #pragma unroll
    for (int mt = 0; mt < MT; mt++)
        #pragma unroll
        for (int nt = 0; nt < NT; nt++)
            #pragma unroll
            for (int j = 0; j < 4; j++) d[mt][nt][j] = 0.f;

    const float4* A4 = (const float4*)Ain;
    const uint2* A2h = (const uint2*)g_a1h;   // 4 halves per uint2; 32 per row
    const uint32_t* Aterm[3] = {As_hi, As_hi, As_lo};
    const uint32_t* Bterm[3] = {Bs_hi, Bs_lo, Bs_hi};

    #pragma unroll
    for (int h = 0; h < 2; h++) {
        __syncthreads();
        #pragma unroll
        for (int t = 0; t < 8; t++) {
            int i = t * 256 + tid;
            int row = i >> 4, c4l = i & 15;
            int gr = row0 + row;
            float4 v = make_float4(0.f, 0.f, 0.f, 0.f);
            if (gr < N_NODES) {
                if (NOUT == 128) {
                    v = A4[(size_t)gr * 32 + h * 16 + c4l];
                } else {
                    uint2 hv = A2h[(size_t)gr * 32 + h * 16 + c4l];
                    float2 f0 = __half22float2(*(__half2*)&hv.x);
                    float2 f1 = __half22float2(*(__half2*)&hv.y);
                    v = make_float4(f0.x, f0.y, f1.x, f1.y);
                }
            }
            *(uint2*)&As_hi[row * STRA + c4l * 2] = make_uint2(pack_hi2(v.x, v.y), pack_hi2(v.z, v.w));
            *(uint2*)&As_lo[row * STRA + c4l * 2] = make_uint2(pack_lo2(v.x, v.y), pack_lo2(v.z, v.w));
        }
        __syncthreads();
        #pragma unroll
        for (int term = 0; term < 3; term++) {
            const uint32_t* Ab = Aterm[term] + (wm * TM + g) * STRA;
            const uint32_t* Bb = Bterm[term] + (wn * 32 + g) * STRB;
            #pragma unroll
            for (int ks = 0; ks < 4; ks++) {
                int koA = ks * 8 + tg;
                int koB = (h * 4 + ks) * 8 + tg;
                uint32_t a[MT][4], b[NT][2];
                #pragma unroll
                for (int mt = 0; mt < MT; mt++) {
                    const uint32_t* Ar = Ab + mt * 16 * STRA;
                    a[mt][0] = Ar[koA];
                    a[mt][1] = Ar[8 * STRA + koA];
                    a[mt][2] = Ar[koA + 4];
                    a[mt][3] = Ar[8 * STRA + koA + 4];
                }
                #pragma unroll
                for (int nt = 0; nt < NT; nt++) {
                    const uint32_t* Br = Bb + nt * 8 * STRB;
                    b[nt][0] = Br[koB];
                    b[nt][1] = Br[koB + 4];
                }
                #pragma unroll
                for (int mt = 0; mt < MT; mt++)
                    #pragma unroll
                    for (int nt = 0; nt < NT; nt++)
                        mma_bf16(d[mt][nt][0], d[mt][nt][1], d[mt][nt][2], d[mt][nt][3],
                                 a[mt][0], a[mt][1], a[mt][2], a[mt][3],
                                 b[nt][0], b[nt][1]);
            }
        }
    }

    #pragma unroll
    for (int mt = 0; mt < MT; mt++) {
        int r0 = row0 + wm * TM + mt * 16 + g;
        #pragma unroll
        for (int nt = 0; nt < NT; nt++) {
            int c = wn * 32 + nt * 8 + tg * 2;
            if (NOUT == 128) {
                if (r0 < N_NODES)
                    *(__half2*)&g_h1h[(size_t)r0 * 128 + c] =
                        __floats2half2_rn(d[mt][nt][0], d[mt][nt][1]);
                if (r0 + 8 < N_NODES)
                    *(__half2*)&g_h1h[(size_t)(r0 + 8) * 128 + c] =
                        __floats2half2_rn(d[mt][nt][2], d[mt][nt][3]);
            } else {
                if (r0 < N_NODES)
                    *(__half2*)&g_h2h[(size_t)r0 * 64 + c] =
                        __floats2half2_rn(d[mt][nt][0], d[mt][nt][1]);
                if (r0 + 8 < N_NODES)
                    *(__half2*)&g_h2h[(size_t)(r0 + 8) * 64 + c] =
                        __floats2half2_rn(d[mt][nt][2], d[mt][nt][3]);
            }
        }
    }
}

// ---------------- agg1: half-warp per node (16 lanes x uint4 = 256B row) ----------------
__global__ __launch_bounds__(256) void k_agg1(const float* __restrict__ b1,
                                              int node0, int node1) {
    int node = node0 + blockIdx.x * 16 + (threadIdx.x >> 4);
    if (node >= node1) return;
    int hl = threadIdx.x & 15;
    float di = g_dinv[node];
    const uint4* H = (const uint4*)g_h1h;
    float acc[8] = {0.f, 0.f, 0.f, 0.f, 0.f, 0.f, 0.f, 0.f};
    uint4 sv = __ldg(&H[(size_t)node * 16 + hl]);
    fma_h8(acc, di, sv);
    int beg = g_rowptr[node];
    int end = g_rowptr[node + 1];
    #pragma unroll 4
    for (int e = beg; e < end; e++) {
        int2 cw = __ldg(&g_cw[e]);
        float w = __int_as_float(cw.y);
        uint4 hv = __ldg(&H[(size_t)cw.x * 16 + hl]);
        fma_h8(acc, w, hv);
    }
    float4 bv0 = ((const float4*)b1)[hl * 2];
    float4 bv1 = ((const float4*)b1)[hl * 2 + 1];
    float o0 = fmaxf(fmaf(acc[0], di, bv0.x), 0.f);
    float o1 = fmaxf(fmaf(acc[1], di, bv0.y), 0.f);
    float o2 = fmaxf(fmaf(acc[2], di, bv0.z), 0.f);
    float o3 = fmaxf(fmaf(acc[3], di, bv0.w), 0.f);
    float o4 = fmaxf(fmaf(acc[4], di, bv1.x), 0.f);
    float o5 = fmaxf(fmaf(acc[5], di, bv1.y), 0.f);
    float o6 = fmaxf(fmaf(acc[6], di, bv1.z), 0.f);
    float o7 = fmaxf(fmaf(acc[7], di, bv1.w), 0.f);
    uint4 packed;
    *(__half2*)&packed.x = __floats2half2_rn(o0, o1);
    *(__half2*)&packed.y = __floats2half2_rn(o2, o3);
    *(__half2*)&packed.z = __floats2half2_rn(o4, o5);
    *(__half2*)&packed.w = __floats2half2_rn(o6, o7);
    ((uint4*)g_a1h)[(size_t)node * 16 + hl] = packed;
}

// ---------------- agg2: quarter-warp per node (8 lanes x uint4 = 128B row) ----------------
__global__ __launch_bounds__(256) void k_agg2(const float* __restrict__ b2,
                                              float* __restrict__ out) {
    int node = blockIdx.x * 32 + (threadIdx.x >> 3);   // grid exact: 3125*32 = 100000
    int ql = threadIdx.x & 7;
    float di = g_dinv[node];
    const uint4* H = (const uint4*)g_h2h;   // 8 uint4 per row
    float acc[8] = {0.f, 0.f, 0.f, 0.f, 0.f, 0.f, 0.f, 0.f};
    uint4 sv = __ldg(&H[(size_t)node * 8 + ql]);
    fma_h8(acc, di, sv);
    int beg = g_rowptr[node];
    int end = g_rowptr[node + 1];
    #pragma unroll 4
    for (int e = beg; e < end; e++) {
        int2 cw = __ldg(&g_cw[e]);
        float w = __int_as_float(cw.y);
        uint4 hv = __ldg(&H[(size_t)cw.x * 8 + ql]);
        fma_h8(acc, w, hv);
    }
    float4 bv0 = ((const float4*)b2)[ql * 2];
    float4 bv1 = ((const float4*)b2)[ql * 2 + 1];
    float v[8];
    v[0] = fmaf(acc[0], di, bv0.x);
    v[1] = fmaf(acc[1], di, bv0.y);
    v[2] = fmaf(acc[2], di, bv0.z);
    v[3] = fmaf(acc[3], di, bv0.w);
    v[4] = fmaf(acc[4], di, bv1.x);
    v[5] = fmaf(acc[5], di, bv1.y);
    v[6] = fmaf(acc[6], di, bv1.z);
    v[7] = fmaf(acc[7], di, bv1.w);

    // log_softmax over 64 values in the quarter-warp (8 lanes x 8)
    float m = v[0];
    #pragma unroll
    for (int j = 1; j < 8; j++) m = fmaxf(m, v[j]);
    #pragma unroll
    for (int o = 4; o > 0; o >>= 1) m = fmaxf(m, __shfl_xor_sync(0xffffffffu, m, o));
    float s = 0.f;
    #pragma unroll
    for (int j = 0; j < 8; j++) s += expf(v[j] - m);
    #pragma unroll
    for (int o = 4; o > 0; o >>= 1) s += __shfl_xor_sync(0xffffffffu, s, o);
    float lse = m + logf(s);
    ((float4*)out)[(size_t)node * 16 + ql * 2] =
        make_float4(v[0] - lse, v[1] - lse, v[2] - lse, v[3] - lse);
    ((float4*)out)[(size_t)node * 16 + ql * 2 + 1] =
        make_float4(v[4] - lse, v[5] - lse, v[6] - lse, v[7] - lse);
}

// ---------------- launch ----------------
extern "C" void kernel_launch(void* const* d_in, const int* in_sizes, int n_in,
                              void* d_out, int out_size) {
    const float* x  = (const float*)d_in[0];
    const int*   ei = (const int*)d_in[1];
    const float* W1 = (const float*)d_in[2];
    const float* b1 = (const float*)d_in[3];
    const float* W2 = (const float*)d_in[4];
    const float* b2 = (const float*)d_in[5];
    float* out = (float*)d_out;

    const int4* src4 = (const int4*)ei;
    const int4* dst4 = (const int4*)(ei + N_EDGES);

    const int SMEM1 = (2 * 128 * 36 + 2 * 128 * 68) * 4;  // 106496
    const int SMEM2 = (2 * 128 * 36 + 2 * 64 * 68) * 4;   //  71680
    cudaFuncSetAttribute(k_mma_gemm<128>, cudaFuncAttributeMaxDynamicSharedMemorySize, SMEM1);
    cudaFuncSetAttribute(k_mma_gemm<64>,  cudaFuncAttributeMaxDynamicSharedMemorySize, SMEM2);

    void* degptr = nullptr;
    cudaGetSymbolAddress(&degptr, g_deg);

    cudaStream_t s1;
    cudaStreamCreateWithFlags(&s1, cudaStreamNonBlocking);
    cudaEvent_t evFork, evG1, evG2;
    cudaEvent_t evA[CHUNKS];
    cudaEventCreateWithFlags(&evFork, cudaEventDisableTiming);
    cudaEventCreateWithFlags(&evG1, cudaEventDisableTiming);
    cudaEventCreateWithFlags(&evG2, cudaEventDisableTiming);
    for (int c = 0; c < CHUNKS; c++) cudaEventCreateWithFlags(&evA[c], cudaEventDisableTiming);

    cudaEventRecord(evFork, 0);
    cudaStreamWaitEvent(s1, evFork, 0);

    // side stream: weight prep + GEMM1
    k_prep_w<<<(128 * 128 + 64 * 128 + 255) / 256, 256, 0, s1>>>(W1, W2);
    k_mma_gemm<128><<<NTILES, 256, SMEM1, s1>>>(x, 0);
    cudaEventRecord(evG1, s1);

    // main stream: CSR build
    cudaMemsetAsync(degptr, 0, N_NODES * sizeof(int));
    k_count<<<(N_EDGES / 4 + 255) / 256, 256>>>(dst4);
    k_scan_part<<<SCAN_BLOCKS, 512>>>();
    k_scan_add2<<<(N_NODES + 512) / 512, 512>>>();
    k_fill<<<(N_EDGES / 4 + 255) / 256, 256>>>(src4, dst4);

    cudaStreamWaitEvent(0, evG1, 0);

    // pipelined agg1 (main) -> gemm2 chunk (side)
    for (int c = 0; c < CHUNKS; c++) {
        int t0 = c * TILES_PER_CHUNK;
        int t1 = (c == CHUNKS - 1) ? NTILES : (c + 1) * TILES_PER_CHUNK;
        int n0 = t0 * 128;
        int n1 = (t1 * 128 < N_NODES) ? t1 * 128 : N_NODES;
        int blocks = (n1 - n0 + 15) / 16;
        k_agg1<<<blocks, 256>>>(b1, n0, n1);
        cudaEventRecord(evA[c], 0);
        cudaStreamWaitEvent(s1, evA[c], 0);
        k_mma_gemm<64><<<t1 - t0, 256, SMEM2, s1>>>(nullptr, t0);
    }
    cudaEventRecord(evG2, s1);
    cudaStreamWaitEvent(0, evG2, 0);

    k_agg2<<<N_NODES / 32, 256>>>(b2, out);
}